// round 6
// baseline (speedup 1.0000x reference)
#include <cuda_runtime.h>
#include <cstddef>

#define IMG_W 256
#define IMG_H 256
#define RPB   64               // output rows per warp-strip
#define STEPS (RPB + 8)        // input rows S-4 .. S+RPB+3

// edge = conv(x,K5)+conv(x,K3) == 2.2*x - 0.19*box3(x) - 0.01*box5(x)
// out  = |maxpool5x5_s1_p2(edge)|   (separable; -inf pool padding)
//
// Vertical-first separable scheme. Persistent per-thread state: input ring
// 5x8, pool pair-chain 4x8, 2-deep prefetch (4 float4). Transients are fused
// in place (v3->v3e, v5->v5e, e->q; no pm5) so peak live regs fit the 128-reg
// cap of launch_bounds(128,4) WITHOUT local-memory spills.

__global__ void __launch_bounds__(128, 4)
fused_edge_pool(const float* __restrict__ x, float* __restrict__ out)
{
    const int lane  = threadIdx.x & 31;
    const int g     = blockIdx.x * 4 + (threadIdx.x >> 5);   // 0..2047
    const int plane = g >> 2;                                // 512 planes
    const int S     = (g & 3) * RPB;                         // 4 strips/plane
    const int c0    = lane << 3;

    const float* __restrict__ xp = x   + (size_t)plane * (IMG_H * IMG_W) + c0;
    float*       __restrict__ op = out + (size_t)plane * (IMG_H * IMG_W) + c0;

    const float    NINF = __int_as_float(0xff800000);
    const unsigned FULL = 0xffffffffu;

    // Input ring: rows rin-4..rin, slot = row mod 5 (static via unroll-by-5).
    float xr[5][8];
#pragma unroll
    for (int i = 0; i < 5; ++i)
#pragma unroll
        for (int j = 0; j < 8; ++j) xr[i][j] = 0.f;

    // Vertical 5-max pair chain: out(r) = max(P3, P1, hm),  P = max(hm_prev, hm).
    float hm_prev[8], P1[8], P2[8], P3[8];
#pragma unroll
    for (int j = 0; j < 8; ++j) { hm_prev[j] = P1[j] = P2[j] = P3[j] = NINF; }

    // 2-deep prefetch shift chain.
    float4 n0a, n0b, n1a, n1b;
    {
        const float4 z = make_float4(0.f, 0.f, 0.f, 0.f);
        int r0 = S - 4, r1 = S - 3;
        n0a = ((unsigned)r0 < IMG_H) ? *reinterpret_cast<const float4*>(xp + r0 * IMG_W)     : z;
        n0b = ((unsigned)r0 < IMG_H) ? *reinterpret_cast<const float4*>(xp + r0 * IMG_W + 4) : z;
        n1a = ((unsigned)r1 < IMG_H) ? *reinterpret_cast<const float4*>(xp + r1 * IMG_W)     : z;
        n1b = ((unsigned)r1 < IMG_H) ? *reinterpret_cast<const float4*>(xp + r1 * IMG_W + 4) : z;
    }

#pragma unroll 1
    for (int ss = 0; ss < STEPS; ss += 5) {
#pragma unroll
        for (int k = 0; k < 5; ++k) {
            const int s = ss + k;
            if (s >= STEPS) break;          // uniform across warp
            const int rin = S - 4 + s;      // input row consumed this step

            const float4 xa = n0a, xb = n0b;
            n0a = n1a; n0b = n1b;
            {
                const int rl = rin + 2;     // prefetch distance 2
                const bool v = ((unsigned)rl < IMG_H) && (s + 2 < STEPS);
                const float4 z = make_float4(0.f, 0.f, 0.f, 0.f);
                n1a = v ? *reinterpret_cast<const float4*>(xp + rl * IMG_W)     : z;
                n1b = v ? *reinterpret_cast<const float4*>(xp + rl * IMG_W + 4) : z;
            }

            // ---- write ring slot k (row rin) ----
            xr[k][0] = xa.x; xr[k][1] = xa.y; xr[k][2] = xa.z; xr[k][3] = xa.w;
            xr[k][4] = xb.x; xr[k][5] = xb.y; xr[k][6] = xb.z; xr[k][7] = xb.w;

            // ---- vertical box sums (edge row re = rin-2), fused into halo arrays ----
            const int a1 = (k + 4) % 5;   // rin-1
            const int a2 = (k + 3) % 5;   // rin-2 (center)
            const int a3 = (k + 2) % 5;   // rin-3
            const int a4 = (k + 1) % 5;   // rin-4
            float v3e[10];                // v3 at cols c0-1 .. c0+8
            float v5e[12];                // v5 at cols c0-2 .. c0+9
#pragma unroll
            for (int j = 0; j < 8; ++j) {
                const float t3 = xr[a1][j] + xr[a2][j] + xr[a3][j];
                v3e[j + 1] = t3;
                v5e[j + 2] = t3 + xr[k][j] + xr[a4][j];
            }

            // halos via shuffles (neighbor lanes' boundary cols)
            v3e[0]  = __shfl_up_sync(FULL, v3e[8], 1);
            v3e[9]  = __shfl_down_sync(FULL, v3e[1], 1);
            v5e[0]  = __shfl_up_sync(FULL, v5e[8], 1);
            v5e[1]  = __shfl_up_sync(FULL, v5e[9], 1);
            v5e[10] = __shfl_down_sync(FULL, v5e[2], 1);
            v5e[11] = __shfl_down_sync(FULL, v5e[3], 1);
            if (lane == 0)  { v3e[0] = 0.f; v5e[0] = 0.f; v5e[1] = 0.f; }   // conv zero pad
            if (lane == 31) { v3e[9] = 0.f; v5e[10] = 0.f; v5e[11] = 0.f; }

            // ---- horizontal sums + edge, written straight into q[2..9] ----
            float q[12];
            {
                float h5 = ((v5e[0] + v5e[1]) + (v5e[2] + v5e[3])) + v5e[4];
#pragma unroll
                for (int j = 0; j < 8; ++j) {
                    if (j > 0) h5 += v5e[j + 4] - v5e[j - 1];   // sliding 5-sum
                    const float h3 = v3e[j] + v3e[j + 1] + v3e[j + 2];
                    q[j + 2] = fmaf(2.2f, xr[a2][j], fmaf(-0.19f, h3, -0.01f * h5));
                }
            }

            // ---- horizontal 5-max halos ----
            q[0]  = __shfl_up_sync(FULL, q[8], 1);
            q[1]  = __shfl_up_sync(FULL, q[9], 1);
            q[10] = __shfl_down_sync(FULL, q[2], 1);
            q[11] = __shfl_down_sync(FULL, q[3], 1);
            if (lane == 0)  { q[0]  = NINF; q[1]  = NINF; }   // pool -inf pad
            if (lane == 31) { q[10] = NINF; q[11] = NINF; }

            float hm[8];
            const int re = rin - 2;
            if (re >= 0 && re < IMG_H) {     // warp-uniform; false only at strip edges
                float pm[10];
#pragma unroll
                for (int i = 0; i < 10; ++i) pm[i] = fmaxf(q[i], q[i + 1]);
#pragma unroll
                for (int j = 0; j < 8; ++j)
                    hm[j] = fmaxf(fmaxf(pm[j], pm[j + 2]), q[j + 4]);
            } else {
#pragma unroll
                for (int j = 0; j < 8; ++j) hm[j] = NINF;
            }

            // ---- vertical 5-max via pair chain + abs, output row r = rin-4 ----
            if (s >= 8) {
                const int r = rin - 4;
                float o[8];
#pragma unroll
                for (int j = 0; j < 8; ++j)
                    o[j] = fabsf(fmaxf(fmaxf(P3[j], P1[j]), hm[j]));
                *reinterpret_cast<float4*>(op + r * IMG_W)     = make_float4(o[0], o[1], o[2], o[3]);
                *reinterpret_cast<float4*>(op + r * IMG_W + 4) = make_float4(o[4], o[5], o[6], o[7]);
            }
#pragma unroll
            for (int j = 0; j < 8; ++j) {
                P3[j] = P2[j]; P2[j] = P1[j];
                P1[j] = fmaxf(hm_prev[j], hm[j]);
                hm_prev[j] = hm[j];
            }
        }
    }
}

extern "C" void kernel_launch(void* const* d_in, const int* in_sizes, int n_in,
                              void* d_out, int out_size)
{
    const float* x = (const float*)d_in[0];
    float* out = (float*)d_out;
    const int planes = in_sizes[0] / (IMG_H * IMG_W);          // 512
    const int warps  = planes * (IMG_H / RPB);                 // 2048
    fused_edge_pool<<<warps / 4, 128>>>(x, out);               // 512 blocks, 1 wave
}